// round 12
// baseline (speedup 1.0000x reference)
#include <cuda_runtime.h>
#include <cuda_fp16.h>
#include <mma.h>

using namespace nvcuda;

#define NN 100000
#define NE 1600000
#define IND 75
#define H 64
#define HB 16
#define NB1 391        // ceil(NN/256)

// Scratch (allocation-free rule: __device__ globals)
__device__ __align__(256) float  g_hA[NN * H];
__device__ __align__(256) float  g_hB[NN * H];
__device__ __align__(256) __half g_P[NN * H];
__device__ __align__(256) float  g_agg[NN * H];
// CSR build
__device__ __align__(256) int    g_deg[NB1 * 256];
__device__ __align__(256) int    g_incl[NB1 * 256];
__device__ __align__(256) int    g_part[512];
__device__ __align__(256) int    g_cursor[NB1 * 256];
__device__ __align__(256) int    g_srcs[NE];
__device__ __align__(256) int    g_dsts[NE];
__device__ __align__(256) __half g_eats[(size_t)NE * HB];

// ---- f32x2 packed helpers -------------------------------------------------
typedef unsigned long long u64t;
__device__ __forceinline__ u64t pk2(float lo, float hi) {
    u64t r; asm("mov.b64 %0, {%1, %2};" : "=l"(r) : "f"(lo), "f"(hi)); return r;
}
__device__ __forceinline__ void upk2(u64t v, float& lo, float& hi) {
    asm("mov.b64 {%0, %1}, %2;" : "=f"(lo), "=f"(hi) : "l"(v));
}
__device__ __forceinline__ u64t fma2(u64t a, u64t b, u64t c) {
    u64t d; asm("fma.rn.f32x2 %0, %1, %2, %3;" : "=l"(d) : "l"(a), "l"(b), "l"(c)); return d;
}

// ---------------------------------------------------------------------------
// CSR build: histogram -> scans -> scatter (stores srcs, dsts, eattr as fp16)
// ---------------------------------------------------------------------------
__global__ void hist_kernel(const int* __restrict__ edst, int* __restrict__ deg) {
    int e = blockIdx.x * blockDim.x + threadIdx.x;
    if (e < NE) {
        int d = edst[e];
        if ((unsigned)d < NN) atomicAdd(&deg[d], 1);
    }
}

__global__ __launch_bounds__(256) void scan1_kernel(const int* __restrict__ deg,
                                                    int* __restrict__ incl,
                                                    int* __restrict__ part) {
    __shared__ int s[256];
    const int i = blockIdx.x * 256 + threadIdx.x;
    int v = (i < NN) ? deg[i] : 0;
    s[threadIdx.x] = v;
    __syncthreads();
#pragma unroll
    for (int o = 1; o < 256; o <<= 1) {
        int t = (threadIdx.x >= o) ? s[threadIdx.x - o] : 0;
        __syncthreads();
        s[threadIdx.x] += t;
        __syncthreads();
    }
    incl[i] = s[threadIdx.x];
    if (threadIdx.x == 255) part[blockIdx.x] = s[255];
}

__global__ __launch_bounds__(512) void scan2_kernel(int* __restrict__ part) {
    __shared__ int s[512];
    int v = (threadIdx.x < NB1) ? part[threadIdx.x] : 0;
    s[threadIdx.x] = v;
    __syncthreads();
#pragma unroll
    for (int o = 1; o < 512; o <<= 1) {
        int t = (threadIdx.x >= o) ? s[threadIdx.x - o] : 0;
        __syncthreads();
        s[threadIdx.x] += t;
        __syncthreads();
    }
    if (threadIdx.x < NB1) part[threadIdx.x] = s[threadIdx.x] - v;  // exclusive
}

__global__ __launch_bounds__(256) void scan3_kernel(const int* __restrict__ deg,
                                                    const int* __restrict__ incl,
                                                    const int* __restrict__ part,
                                                    int* __restrict__ cursor) {
    const int i = blockIdx.x * 256 + threadIdx.x;
    if (i < NN) cursor[i] = incl[i] - deg[i] + part[blockIdx.x];
}

__global__ void scatter_kernel(const int* __restrict__ esrc,
                               const int* __restrict__ edst,
                               const float* __restrict__ eattr,
                               int* __restrict__ cursor,
                               int* __restrict__ srcs,
                               int* __restrict__ dsts,
                               __half* __restrict__ eats) {
    int e = blockIdx.x * blockDim.x + threadIdx.x;
    if (e >= NE) return;
    const int s = esrc[e], d = edst[e];
    if ((unsigned)s >= NN || (unsigned)d >= NN) return;
    int pos = atomicAdd(&cursor[d], 1);
    srcs[pos] = s;
    dsts[pos] = d;
    const float4* a = (const float4*)(eattr + (size_t)e * HB);
    const float4 v0 = a[0], v1 = a[1], v2 = a[2], v3 = a[3];
    __half2 h0 = __floats2half2_rn(v0.x, v0.y), h1 = __floats2half2_rn(v0.z, v0.w);
    __half2 h2 = __floats2half2_rn(v1.x, v1.y), h3 = __floats2half2_rn(v1.z, v1.w);
    __half2 h4 = __floats2half2_rn(v2.x, v2.y), h5 = __floats2half2_rn(v2.z, v2.w);
    __half2 h6 = __floats2half2_rn(v3.x, v3.y), h7 = __floats2half2_rn(v3.z, v3.w);
    uint4 p0, p1;
    p0.x = *(unsigned*)&h0; p0.y = *(unsigned*)&h1;
    p0.z = *(unsigned*)&h2; p0.w = *(unsigned*)&h3;
    p1.x = *(unsigned*)&h4; p1.y = *(unsigned*)&h5;
    p1.z = *(unsigned*)&h6; p1.w = *(unsigned*)&h7;
    uint4* b = (uint4*)(eats + (size_t)pos * HB);
    b[0] = p0; b[1] = p1;
}

// ---------------------------------------------------------------------------
// proj: out = x @ W(75x64) + b     (run once)
// ---------------------------------------------------------------------------
__global__ __launch_bounds__(256) void proj_kernel(const float* __restrict__ x,
                                                   const float* __restrict__ w,
                                                   const float* __restrict__ b,
                                                   float* __restrict__ out) {
    __shared__ float sW[IND][H];
    __shared__ float sA[32][IND + 1];
    for (int i = threadIdx.x; i < IND * H; i += 256) sW[i / H][i % H] = w[i];

    const int lane = threadIdx.x & 31, wid = threadIdx.x >> 5;
    const int nl = lane & 3, cg = lane >> 2;
    const int myn = wid * 4 + nl;
    const float4 bb0 = *(const float4*)&b[cg * 8];
    const float4 bb1 = *(const float4*)&b[cg * 8 + 4];

    for (int tile = blockIdx.x; tile < NN / 32; tile += gridDim.x) {
        const int base = tile * 32;
        __syncthreads();
        for (int i = threadIdx.x; i < 32 * IND; i += 256)
            sA[i / IND][i % IND] = x[(size_t)base * IND + i];
        __syncthreads();

        float acc[8] = {bb0.x, bb0.y, bb0.z, bb0.w, bb1.x, bb1.y, bb1.z, bb1.w};
#pragma unroll 5
        for (int k = 0; k < IND; k++) {
            const float a = sA[myn][k];
            const float4 w0 = *(const float4*)&sW[k][cg * 8];
            const float4 w1 = *(const float4*)&sW[k][cg * 8 + 4];
            acc[0] += a * w0.x; acc[1] += a * w0.y; acc[2] += a * w0.z; acc[3] += a * w0.w;
            acc[4] += a * w1.x; acc[5] += a * w1.y; acc[6] += a * w1.z; acc[7] += a * w1.w;
        }
        const size_t o = (size_t)(base + myn) * H + cg * 8;
        *(float4*)&out[o]     = make_float4(acc[0], acc[1], acc[2], acc[3]);
        *(float4*)&out[o + 4] = make_float4(acc[4], acc[5], acc[6], acc[7]);
    }
}

// ---------------------------------------------------------------------------
// pk (scalar + f32x2): P(fp16) = h @ W2h(64x64) + b2, zero agg (fused).
// ---------------------------------------------------------------------------
__global__ __launch_bounds__(256) void pk_kernel(const float* __restrict__ h,
                                                 const float* __restrict__ w,
                                                 const float* __restrict__ b,
                                                 __half* __restrict__ P,
                                                 float* __restrict__ agg) {
    __shared__ float sW[H][H];
    __shared__ float sA[32][H + 1];
    for (int i = threadIdx.x; i < H * H; i += 256) sW[i >> 6][i & 63] = w[i];

    const int lane = threadIdx.x & 31, wid = threadIdx.x >> 5;
    const int nl = lane & 3, cg = lane >> 2;
    const int myn = wid * 4 + nl;
    const float4 bb0 = *(const float4*)&b[cg * 8];
    const float4 bb1 = *(const float4*)&b[cg * 8 + 4];
    const float4 z4 = make_float4(0.f, 0.f, 0.f, 0.f);

    for (int tile = blockIdx.x; tile < NN / 32; tile += gridDim.x) {
        const int base = tile * 32;
        __syncthreads();
        for (int i = threadIdx.x; i < 32 * H; i += 256)
            sA[i >> 6][i & 63] = h[(size_t)base * H + i];
        __syncthreads();

        u64t acc[4] = {pk2(bb0.x, bb0.y), pk2(bb0.z, bb0.w),
                       pk2(bb1.x, bb1.y), pk2(bb1.z, bb1.w)};
#pragma unroll 8
        for (int k = 0; k < H; k++) {
            const float a = sA[myn][k];
            const u64t aa = pk2(a, a);
            const ulonglong2 w0 = *(const ulonglong2*)&sW[k][cg * 8];
            const ulonglong2 w1 = *(const ulonglong2*)&sW[k][cg * 8 + 4];
            acc[0] = fma2(aa, w0.x, acc[0]);
            acc[1] = fma2(aa, w0.y, acc[1]);
            acc[2] = fma2(aa, w1.x, acc[2]);
            acc[3] = fma2(aa, w1.y, acc[3]);
        }
        float l0, h0, l1, h1, l2, h2, l3, h3;
        upk2(acc[0], l0, h0); upk2(acc[1], l1, h1);
        upk2(acc[2], l2, h2); upk2(acc[3], l3, h3);
        __half2 p0 = __floats2half2_rn(l0, h0);
        __half2 p1 = __floats2half2_rn(l1, h1);
        __half2 p2 = __floats2half2_rn(l2, h2);
        __half2 p3 = __floats2half2_rn(l3, h3);
        uint4 pr;
        pr.x = *(unsigned*)&p0; pr.y = *(unsigned*)&p1;
        pr.z = *(unsigned*)&p2; pr.w = *(unsigned*)&p3;
        *(uint4*)(P + (size_t)(base + myn) * H + cg * 8) = pr;

        const size_t o = (size_t)(base + myn) * H + cg * 8;
        *(float4*)&agg[o]     = z4;
        *(float4*)&agg[o + 4] = z4;
    }
}

// ---------------------------------------------------------------------------
// edge (HMMA + dst-sorted merge): warp = 16 CSR-ordered edges.
// fp16 eats tile -> wmma vs reg-resident W2e -> m = leakyrelu(P[src]+B);
// half-warp walks 8 consecutive rows, merges equal-dst runs in registers,
// one red.global.add.v4 per run.
// ---------------------------------------------------------------------------
__global__ __launch_bounds__(256) void edge_kernel(const int* __restrict__ srcs,
                                                   const int* __restrict__ dsts,
                                                   const __half* __restrict__ eats,
                                                   const float* __restrict__ w2e,
                                                   const __half* __restrict__ P,
                                                   float* __restrict__ agg) {
    __shared__ __half sW[HB * H];              // 2048 B
    __shared__ __half sA[8][HB * HB];          // 8 x 512 B
    __shared__ float  sB[8][HB * H];           // 8 x 4096 B

    for (int i = threadIdx.x; i < HB * H; i += 256) sW[i] = __float2half(w2e[i]);
    __syncthreads();

    const int lane = threadIdx.x & 31, wid = threadIdx.x >> 5;
    const int half = lane >> 4, hl = lane & 15;
    const int cbase = hl * 4;

    wmma::fragment<wmma::matrix_b, 16, 16, 16, __half, wmma::row_major> fw[4];
#pragma unroll
    for (int nt = 0; nt < 4; nt++)
        wmma::load_matrix_sync(fw[nt], &sW[nt * 16], H);

    __half* const myA = sA[wid];
    float*  const myB = sB[wid];
    const int arow = lane >> 1, acol = (lane & 1) * 8;   // 8 halves = 16 B

    const int gw = blockIdx.x * 8 + wid;
    const int nw = gridDim.x * 8;

    for (int t = gw; t < NE / 16; t += nw) {
        const int pbase = t * 16;

        // stage fp16 eats tile directly (no conversion)
        *(uint4*)(myA + arow * HB + acol) =
            *(const uint4*)(eats + (size_t)(pbase + arow) * HB + acol);
        __syncwarp();

        wmma::fragment<wmma::matrix_a, 16, 16, 16, __half, wmma::row_major> fa;
        wmma::load_matrix_sync(fa, myA, HB);
#pragma unroll
        for (int nt = 0; nt < 4; nt++) {
            wmma::fragment<wmma::accumulator, 16, 16, 16, float> fc;
            wmma::fill_fragment(fc, 0.f);
            wmma::mma_sync(fc, fa, fw[nt], fc);
            wmma::store_matrix_sync(&myB[nt * 16], fc, H, wmma::mem_row_major);
        }
        __syncwarp();

        // scatter with run merging: half-warp walks rows half*8 .. half*8+7
        int prev = -1;
        float4 racc = make_float4(0.f, 0.f, 0.f, 0.f);
#pragma unroll
        for (int r = 0; r < 8; r++) {
            const int row = half * 8 + r;
            const int pos = pbase + row;
            const int dst = dsts[pos];
            const int src = srcs[pos];

            const float4 bv = *(const float4*)(myB + row * H + cbase);
            const uint2 praw = *(const uint2*)(P + (size_t)src * H + cbase);
            const float2 pa = __half22float2(*(const __half2*)&praw.x);
            const float2 pb = __half22float2(*(const __half2*)&praw.y);

            float m0 = pa.x + bv.x, m1 = pa.y + bv.y;
            float m2 = pb.x + bv.z, m3 = pb.y + bv.w;
            m0 = fmaxf(m0, 0.1f * m0);
            m1 = fmaxf(m1, 0.1f * m1);
            m2 = fmaxf(m2, 0.1f * m2);
            m3 = fmaxf(m3, 0.1f * m3);

            if (dst != prev) {
                if (prev >= 0) {
                    float* dp = agg + (size_t)prev * H + cbase;
                    asm volatile("red.global.add.v4.f32 [%0], {%1, %2, %3, %4};"
                                 :: "l"(dp), "f"(racc.x), "f"(racc.y),
                                    "f"(racc.z), "f"(racc.w) : "memory");
                }
                racc = make_float4(m0, m1, m2, m3);
                prev = dst;
            } else {
                racc.x += m0; racc.y += m1; racc.z += m2; racc.w += m3;
            }
        }
        {
            float* dp = agg + (size_t)prev * H + cbase;
            asm volatile("red.global.add.v4.f32 [%0], {%1, %2, %3, %4};"
                         :: "l"(dp), "f"(racc.x), "f"(racc.y),
                            "f"(racc.z), "f"(racc.w) : "memory");
        }
        __syncwarp();
    }
}

// ---------------------------------------------------------------------------
// upd (scalar + f32x2): out = concat(h, agg) @ W1(128x64) + b1
// ---------------------------------------------------------------------------
__global__ __launch_bounds__(256) void upd_kernel(const float* __restrict__ h,
                                                  const float* __restrict__ agg,
                                                  const float* __restrict__ w,
                                                  const float* __restrict__ b,
                                                  float* __restrict__ out) {
    __shared__ float sW[2 * H][H];   // 32768 B
    __shared__ float sA[32][2 * H];  // 16384 B, XOR-swizzled by (row&3)<<3
    for (int i = threadIdx.x; i < 2 * H * H; i += 256) sW[i >> 6][i & 63] = w[i];

    const int lane = threadIdx.x & 31, wid = threadIdx.x >> 5;
    const int nl = lane & 3, cg = lane >> 2;
    const int myn = wid * 4 + nl;
    const int swz = nl << 3;
    const float4 bb0 = *(const float4*)&b[cg * 8];
    const float4 bb1 = *(const float4*)&b[cg * 8 + 4];

    for (int tile = blockIdx.x; tile < NN / 32; tile += gridDim.x) {
        const int base = tile * 32;
        __syncthreads();
        for (int i = threadIdx.x; i < 32 * H; i += 256) {
            const int r = i >> 6, c = i & 63;
            const int s = (r & 3) << 3;
            sA[r][c ^ s]        = h[(size_t)base * H + i];
            sA[r][(c + 64) ^ s] = agg[(size_t)base * H + i];
        }
        __syncthreads();

        u64t acc[4] = {pk2(bb0.x, bb0.y), pk2(bb0.z, bb0.w),
                       pk2(bb1.x, bb1.y), pk2(bb1.z, bb1.w)};
#pragma unroll 8
        for (int k = 0; k < 2 * H; k++) {
            const float a = sA[myn][k ^ swz];
            const u64t aa = pk2(a, a);
            const ulonglong2 w0 = *(const ulonglong2*)&sW[k][cg * 8];
            const ulonglong2 w1 = *(const ulonglong2*)&sW[k][cg * 8 + 4];
            acc[0] = fma2(aa, w0.x, acc[0]);
            acc[1] = fma2(aa, w0.y, acc[1]);
            acc[2] = fma2(aa, w1.x, acc[2]);
            acc[3] = fma2(aa, w1.y, acc[3]);
        }
        float o0, o1, o2, o3, o4, o5, o6, o7;
        upk2(acc[0], o0, o1); upk2(acc[1], o2, o3);
        upk2(acc[2], o4, o5); upk2(acc[3], o6, o7);
        const size_t o = (size_t)(base + myn) * H + cg * 8;
        *(float4*)&out[o]     = make_float4(o0, o1, o2, o3);
        *(float4*)&out[o + 4] = make_float4(o4, o5, o6, o7);
    }
}

// ---------------------------------------------------------------------------
extern "C" void kernel_launch(void* const* d_in, const int* in_sizes, int n_in,
                              void* d_out, int out_size) {
    const float* x      = (const float*)d_in[0];   // [100000, 75]
    const int*   eidx   = (const int*)d_in[1];     // [2, 1600000] (int64 -> int32)
    const float* eattr  = (const float*)d_in[2];   // [1600000, 16]
    const float* proj_w = (const float*)d_in[3];
    const float* proj_b = (const float*)d_in[4];
    const float* u2w    = (const float*)d_in[5];   // [3, 80, 64]
    const float* u2b    = (const float*)d_in[6];
    const float* u1w    = (const float*)d_in[7];   // [3, 128, 64]
    const float* u1b    = (const float*)d_in[8];
    float*       out    = (float*)d_out;           // [100000, 64]

    float *hA, *hB, *agg;
    __half *P, *eats;
    int *deg, *incl, *part, *cursor, *srcs, *dsts;
    cudaGetSymbolAddress((void**)&hA, g_hA);
    cudaGetSymbolAddress((void**)&hB, g_hB);
    cudaGetSymbolAddress((void**)&P, g_P);
    cudaGetSymbolAddress((void**)&agg, g_agg);
    cudaGetSymbolAddress((void**)&deg, g_deg);
    cudaGetSymbolAddress((void**)&incl, g_incl);
    cudaGetSymbolAddress((void**)&part, g_part);
    cudaGetSymbolAddress((void**)&cursor, g_cursor);
    cudaGetSymbolAddress((void**)&srcs, g_srcs);
    cudaGetSymbolAddress((void**)&dsts, g_dsts);
    cudaGetSymbolAddress((void**)&eats, g_eats);

    const int* esrc = eidx;
    const int* edst = eidx + NE;

    // CSR build (once per launch)
    cudaMemsetAsync(deg, 0, NB1 * 256 * sizeof(int));
    hist_kernel<<<(NE + 255) / 256, 256>>>(edst, deg);
    scan1_kernel<<<NB1, 256>>>(deg, incl, part);
    scan2_kernel<<<1, 512>>>(part);
    scan3_kernel<<<NB1, 256>>>(deg, incl, part, cursor);
    scatter_kernel<<<(NE + 255) / 256, 256>>>(esrc, edst, eattr, cursor, srcs, dsts, eats);

    proj_kernel<<<592, 256>>>(x, proj_w, proj_b, hA);

    for (int l = 0; l < 3; l++) {
        const float* hin = (l == 1) ? hB : hA;          // l0:A, l1:B, l2:A
        float* hout = (l == 0) ? hB : ((l == 1) ? hA : out);
        const float* w2 = u2w + (size_t)l * 80 * 64;     // rows 0..63 = W2h, 64..79 = W2e
        pk_kernel<<<592, 256>>>(hin, w2, u2b + l * 64, P, agg);
        edge_kernel<<<1184, 256>>>(srcs, dsts, eats, w2 + 64 * 64, P, agg);
        upd_kernel<<<592, 256>>>(hin, agg, u1w + (size_t)l * 128 * 64, u1b + l * 64, hout);
    }
}

// round 13
// speedup vs baseline: 1.0970x; 1.0970x over previous
#include <cuda_runtime.h>
#include <cuda_fp16.h>
#include <mma.h>

using namespace nvcuda;

#define NN 100000
#define NE 1600000
#define IND 75
#define H 64
#define HB 16

// Scratch (allocation-free rule: __device__ globals)
__device__ __align__(256) float  g_hA[NN * H];
__device__ __align__(256) float  g_hB[NN * H];
__device__ __align__(256) __half g_P[NN * H];
__device__ __align__(256) float  g_agg[NN * H];

// ---- f32x2 packed helpers -------------------------------------------------
typedef unsigned long long u64t;
__device__ __forceinline__ u64t pk2(float lo, float hi) {
    u64t r; asm("mov.b64 %0, {%1, %2};" : "=l"(r) : "f"(lo), "f"(hi)); return r;
}
__device__ __forceinline__ void upk2(u64t v, float& lo, float& hi) {
    asm("mov.b64 {%0, %1}, %2;" : "=f"(lo), "=f"(hi) : "l"(v));
}
__device__ __forceinline__ u64t fma2(u64t a, u64t b, u64t c) {
    u64t d; asm("fma.rn.f32x2 %0, %1, %2, %3;" : "=l"(d) : "l"(a), "l"(b), "l"(c)); return d;
}

// ---------------------------------------------------------------------------
// proj: out = x @ W(75x64) + b     (run once)
// ---------------------------------------------------------------------------
__global__ __launch_bounds__(256) void proj_kernel(const float* __restrict__ x,
                                                   const float* __restrict__ w,
                                                   const float* __restrict__ b,
                                                   float* __restrict__ out) {
    __shared__ float sW[IND][H];
    __shared__ float sA[32][IND + 1];
    for (int i = threadIdx.x; i < IND * H; i += 256) sW[i / H][i % H] = w[i];

    const int lane = threadIdx.x & 31, wid = threadIdx.x >> 5;
    const int nl = lane & 3, cg = lane >> 2;
    const int myn = wid * 4 + nl;
    const float4 bb0 = *(const float4*)&b[cg * 8];
    const float4 bb1 = *(const float4*)&b[cg * 8 + 4];

    for (int tile = blockIdx.x; tile < NN / 32; tile += gridDim.x) {
        const int base = tile * 32;
        __syncthreads();
        for (int i = threadIdx.x; i < 32 * IND; i += 256)
            sA[i / IND][i % IND] = x[(size_t)base * IND + i];
        __syncthreads();

        float acc[8] = {bb0.x, bb0.y, bb0.z, bb0.w, bb1.x, bb1.y, bb1.z, bb1.w};
#pragma unroll 5
        for (int k = 0; k < IND; k++) {
            const float a = sA[myn][k];
            const float4 w0 = *(const float4*)&sW[k][cg * 8];
            const float4 w1 = *(const float4*)&sW[k][cg * 8 + 4];
            acc[0] += a * w0.x; acc[1] += a * w0.y; acc[2] += a * w0.z; acc[3] += a * w0.w;
            acc[4] += a * w1.x; acc[5] += a * w1.y; acc[6] += a * w1.z; acc[7] += a * w1.w;
        }
        const size_t o = (size_t)(base + myn) * H + cg * 8;
        *(float4*)&out[o]     = make_float4(acc[0], acc[1], acc[2], acc[3]);
        *(float4*)&out[o + 4] = make_float4(acc[4], acc[5], acc[6], acc[7]);
    }
}

// ---------------------------------------------------------------------------
// pk v3: P(fp16) = h @ W2h(64x64) + b2, zero agg. 64-node tile, warp=8 nodes,
// lane = 2 nodes x 8 cols. Act reads swizzled by (node&7)*4 -> 4 distinct banks.
// ---------------------------------------------------------------------------
__global__ __launch_bounds__(256) void pk_kernel(const float* __restrict__ h,
                                                 const float* __restrict__ w,
                                                 const float* __restrict__ b,
                                                 __half* __restrict__ P,
                                                 float* __restrict__ agg) {
    __shared__ float sW[H][H];       // 16 KB
    __shared__ float sA[64 * 64];    // 16 KB, swizzled
    for (int i = threadIdx.x; i < H * H; i += 256) sW[i >> 6][i & 63] = w[i];

    const int lane = threadIdx.x & 31, wid = threadIdx.x >> 5;
    const int nl = lane & 3, cg = lane >> 2;
    const int ln0 = (wid << 3) + (nl << 1), ln1 = ln0 + 1;
    const int sw0 = (ln0 & 7) * 4, sw1 = (ln1 & 7) * 4;
    const float4 bb0 = *(const float4*)&b[cg * 8];
    const float4 bb1 = *(const float4*)&b[cg * 8 + 4];

    const int snd = threadIdx.x >> 2, sq = threadIdx.x & 3;  // staging coords
    const int ntiles = (NN + 63) / 64;
    const float4 z4 = make_float4(0.f, 0.f, 0.f, 0.f);

    for (int tile = blockIdx.x; tile < ntiles; tile += gridDim.x) {
        const int nbase = tile * 64;
        __syncthreads();
        {   // stage h[nbase..nbase+63][0..63] row-major, k ^ (node&7)*4
            const int gn = nbase + snd;
            const int ssw = (snd & 7) * 4;
            if (gn < NN) {
#pragma unroll
                for (int j = 0; j < 4; j++) {
                    const int kk = sq * 16 + j * 4;
                    float4 v = *(const float4*)(h + (size_t)gn * H + kk);
                    *(float4*)&sA[snd * 64 + (kk ^ ssw)] = v;
                }
            } else {
#pragma unroll
                for (int j = 0; j < 4; j++)
                    *(float4*)&sA[snd * 64 + ((sq * 16 + j * 4) ^ ssw)] = z4;
            }
        }
        __syncthreads();

        u64t a0c[4] = {pk2(bb0.x, bb0.y), pk2(bb0.z, bb0.w),
                       pk2(bb1.x, bb1.y), pk2(bb1.z, bb1.w)};
        u64t a1c[4] = {a0c[0], a0c[1], a0c[2], a0c[3]};
#pragma unroll 8
        for (int k = 0; k < H; k++) {
            const ulonglong2 w0 = *(const ulonglong2*)&sW[k][cg * 8];
            const ulonglong2 w1 = *(const ulonglong2*)&sW[k][cg * 8 + 4];
            const float a0 = sA[ln0 * 64 + (k ^ sw0)];
            const float a1 = sA[ln1 * 64 + (k ^ sw1)];
            const u64t aa0 = pk2(a0, a0), aa1 = pk2(a1, a1);
            a0c[0] = fma2(aa0, w0.x, a0c[0]); a0c[1] = fma2(aa0, w0.y, a0c[1]);
            a0c[2] = fma2(aa0, w1.x, a0c[2]); a0c[3] = fma2(aa0, w1.y, a0c[3]);
            a1c[0] = fma2(aa1, w0.x, a1c[0]); a1c[1] = fma2(aa1, w0.y, a1c[1]);
            a1c[2] = fma2(aa1, w1.x, a1c[2]); a1c[3] = fma2(aa1, w1.y, a1c[3]);
        }
        // store fp16 P rows
#pragma unroll
        for (int n = 0; n < 2; n++) {
            const int gn = nbase + ((n == 0) ? ln0 : ln1);
            if (gn >= NN) continue;
            const u64t* ac = (n == 0) ? a0c : a1c;
            float f0, f1, f2, f3, f4, f5, f6, f7;
            upk2(ac[0], f0, f1); upk2(ac[1], f2, f3);
            upk2(ac[2], f4, f5); upk2(ac[3], f6, f7);
            __half2 p0 = __floats2half2_rn(f0, f1);
            __half2 p1 = __floats2half2_rn(f2, f3);
            __half2 p2 = __floats2half2_rn(f4, f5);
            __half2 p3 = __floats2half2_rn(f6, f7);
            uint4 pr;
            pr.x = *(unsigned*)&p0; pr.y = *(unsigned*)&p1;
            pr.z = *(unsigned*)&p2; pr.w = *(unsigned*)&p3;
            *(uint4*)(P + (size_t)gn * H + cg * 8) = pr;
        }
        // zero agg: 1024 float4 over 256 threads
#pragma unroll
        for (int j = 0; j < 4; j++) {
            const int f = threadIdx.x * 4 + j;          // float4 index in tile
            const int node = nbase + (f >> 4);
            if (node < NN)
                *((float4*)(agg + (size_t)nbase * H) + f) = z4;
        }
    }
}

// ---------------------------------------------------------------------------
// edge (HMMA, R11): warp handles 16 edges; eattr -> fp16 -> wmma vs
// reg-resident W2e; scatter agg[dst] +=red leakyrelu(P_fp16[src] + Brow).
// ---------------------------------------------------------------------------
__global__ __launch_bounds__(256) void edge_kernel(const int* __restrict__ esrc,
                                                   const int* __restrict__ edst,
                                                   const float* __restrict__ eattr,
                                                   const float* __restrict__ w2e,
                                                   const __half* __restrict__ P,
                                                   float* __restrict__ agg) {
    __shared__ __half sW[HB * H];              // 2048 B
    __shared__ __half sA[8][HB * HB];          // 8 x 512 B
    __shared__ float  sB[8][HB * H];           // 8 x 4096 B

    for (int i = threadIdx.x; i < HB * H; i += 256) sW[i] = __float2half(w2e[i]);
    __syncthreads();

    const int lane = threadIdx.x & 31, wid = threadIdx.x >> 5;
    const int half = lane >> 4, hl = lane & 15;
    const int cbase = hl * 4;

    wmma::fragment<wmma::matrix_b, 16, 16, 16, __half, wmma::row_major> fw[4];
#pragma unroll
    for (int nt = 0; nt < 4; nt++)
        wmma::load_matrix_sync(fw[nt], &sW[nt * 16], H);

    __half* const myA = sA[wid];
    float*  const myB = sB[wid];
    const int arow = lane >> 1, acol = (lane & 1) * 8;

    const int gw = blockIdx.x * 8 + wid;
    const int nw = gridDim.x * 8;

    for (int t = gw; t < NE / 16; t += nw) {
        const int ebase = t * 16;
        {
            const float4* src = (const float4*)(eattr + (size_t)(ebase + arow) * HB + acol);
            const float4 v0 = src[0], v1 = src[1];
            __half2 h0 = __floats2half2_rn(v0.x, v0.y);
            __half2 h1 = __floats2half2_rn(v0.z, v0.w);
            __half2 h2 = __floats2half2_rn(v1.x, v1.y);
            __half2 h3 = __floats2half2_rn(v1.z, v1.w);
            uint4 pk;
            pk.x = *(unsigned*)&h0; pk.y = *(unsigned*)&h1;
            pk.z = *(unsigned*)&h2; pk.w = *(unsigned*)&h3;
            *(uint4*)(myA + arow * HB + acol) = pk;
        }
        __syncwarp();

        wmma::fragment<wmma::matrix_a, 16, 16, 16, __half, wmma::row_major> fa;
        wmma::load_matrix_sync(fa, myA, HB);
#pragma unroll
        for (int nt = 0; nt < 4; nt++) {
            wmma::fragment<wmma::accumulator, 16, 16, 16, float> fc;
            wmma::fill_fragment(fc, 0.f);
            wmma::mma_sync(fc, fa, fw[nt], fc);
            wmma::store_matrix_sync(&myB[nt * 16], fc, H, wmma::mem_row_major);
        }
        __syncwarp();

#pragma unroll
        for (int r = 0; r < 8; r++) {
            const int el = 2 * r + half;
            const int e = ebase + el;
            const int src = esrc[e];
            const int dst = edst[e];
            if ((unsigned)src >= NN || (unsigned)dst >= NN) continue;

            const float4 bv = *(const float4*)(myB + el * H + cbase);
            const uint2 praw = *(const uint2*)(P + (size_t)src * H + cbase);
            const float2 pa = __half22float2(*(const __half2*)&praw.x);
            const float2 pb = __half22float2(*(const __half2*)&praw.y);

            float m0 = pa.x + bv.x, m1 = pa.y + bv.y;
            float m2 = pb.x + bv.z, m3 = pb.y + bv.w;
            m0 = fmaxf(m0, 0.1f * m0);
            m1 = fmaxf(m1, 0.1f * m1);
            m2 = fmaxf(m2, 0.1f * m2);
            m3 = fmaxf(m3, 0.1f * m3);

            float* dp = agg + (size_t)dst * H + cbase;
            asm volatile("red.global.add.v4.f32 [%0], {%1, %2, %3, %4};"
                         :: "l"(dp), "f"(m0), "f"(m1), "f"(m2), "f"(m3)
                         : "memory");
        }
        __syncwarp();
    }
}

// ---------------------------------------------------------------------------
// upd v3: out = concat(h, agg) @ W1(128x64) + b1. 64-node tile, warp=8 nodes,
// lane = 2 nodes x 8 cols. K=128 in two 64-col chunks (h, agg).
// smem: sW 32KB + sA 16KB = 48KB exactly.
// ---------------------------------------------------------------------------
__global__ __launch_bounds__(256) void upd_kernel(const float* __restrict__ h,
                                                  const float* __restrict__ agg,
                                                  const float* __restrict__ w,
                                                  const float* __restrict__ b,
                                                  float* __restrict__ out) {
    __shared__ float sW[2 * H][H];   // 32 KB
    __shared__ float sA[64 * 64];    // 16 KB, swizzled
    for (int i = threadIdx.x; i < 2 * H * H; i += 256) sW[i >> 6][i & 63] = w[i];

    const int lane = threadIdx.x & 31, wid = threadIdx.x >> 5;
    const int nl = lane & 3, cg = lane >> 2;
    const int ln0 = (wid << 3) + (nl << 1), ln1 = ln0 + 1;
    const int sw0 = (ln0 & 7) * 4, sw1 = (ln1 & 7) * 4;
    const float4 bb0 = *(const float4*)&b[cg * 8];
    const float4 bb1 = *(const float4*)&b[cg * 8 + 4];

    const int snd = threadIdx.x >> 2, sq = threadIdx.x & 3;
    const int ntiles = (NN + 63) / 64;
    const float4 z4 = make_float4(0.f, 0.f, 0.f, 0.f);

    for (int tile = blockIdx.x; tile < ntiles; tile += gridDim.x) {
        const int nbase = tile * 64;
        u64t a0c[4] = {pk2(bb0.x, bb0.y), pk2(bb0.z, bb0.w),
                       pk2(bb1.x, bb1.y), pk2(bb1.z, bb1.w)};
        u64t a1c[4] = {a0c[0], a0c[1], a0c[2], a0c[3]};

#pragma unroll
        for (int ch = 0; ch < 2; ch++) {
            const float* srcm = (ch == 0) ? h : agg;
            __syncthreads();
            {
                const int gn = nbase + snd;
                const int ssw = (snd & 7) * 4;
                if (gn < NN) {
#pragma unroll
                    for (int j = 0; j < 4; j++) {
                        const int kk = sq * 16 + j * 4;
                        float4 v = *(const float4*)(srcm + (size_t)gn * H + kk);
                        *(float4*)&sA[snd * 64 + (kk ^ ssw)] = v;
                    }
                } else {
#pragma unroll
                    for (int j = 0; j < 4; j++)
                        *(float4*)&sA[snd * 64 + ((sq * 16 + j * 4) ^ ssw)] = z4;
                }
            }
            __syncthreads();

#pragma unroll 8
            for (int k = 0; k < H; k++) {
                const int wrow = ch * H + k;
                const ulonglong2 w0 = *(const ulonglong2*)&sW[wrow][cg * 8];
                const ulonglong2 w1 = *(const ulonglong2*)&sW[wrow][cg * 8 + 4];
                const float a0 = sA[ln0 * 64 + (k ^ sw0)];
                const float a1 = sA[ln1 * 64 + (k ^ sw1)];
                const u64t aa0 = pk2(a0, a0), aa1 = pk2(a1, a1);
                a0c[0] = fma2(aa0, w0.x, a0c[0]); a0c[1] = fma2(aa0, w0.y, a0c[1]);
                a0c[2] = fma2(aa0, w1.x, a0c[2]); a0c[3] = fma2(aa0, w1.y, a0c[3]);
                a1c[0] = fma2(aa1, w0.x, a1c[0]); a1c[1] = fma2(aa1, w0.y, a1c[1]);
                a1c[2] = fma2(aa1, w1.x, a1c[2]); a1c[3] = fma2(aa1, w1.y, a1c[3]);
            }
        }

#pragma unroll
        for (int n = 0; n < 2; n++) {
            const int gn = nbase + ((n == 0) ? ln0 : ln1);
            if (gn >= NN) continue;
            const u64t* ac = (n == 0) ? a0c : a1c;
            float f0, f1, f2, f3, f4, f5, f6, f7;
            upk2(ac[0], f0, f1); upk2(ac[1], f2, f3);
            upk2(ac[2], f4, f5); upk2(ac[3], f6, f7);
            float* op = out + (size_t)gn * H + cg * 8;
            *(float4*)op       = make_float4(f0, f1, f2, f3);
            *(float4*)(op + 4) = make_float4(f4, f5, f6, f7);
        }
    }
}

// ---------------------------------------------------------------------------
extern "C" void kernel_launch(void* const* d_in, const int* in_sizes, int n_in,
                              void* d_out, int out_size) {
    const float* x      = (const float*)d_in[0];   // [100000, 75]
    const int*   eidx   = (const int*)d_in[1];     // [2, 1600000] (int64 -> int32)
    const float* eattr  = (const float*)d_in[2];   // [1600000, 16]
    const float* proj_w = (const float*)d_in[3];
    const float* proj_b = (const float*)d_in[4];
    const float* u2w    = (const float*)d_in[5];   // [3, 80, 64]
    const float* u2b    = (const float*)d_in[6];
    const float* u1w    = (const float*)d_in[7];   // [3, 128, 64]
    const float* u1b    = (const float*)d_in[8];
    float*       out    = (float*)d_out;           // [100000, 64]

    float *hA, *hB, *agg;
    __half* P;
    cudaGetSymbolAddress((void**)&hA, g_hA);
    cudaGetSymbolAddress((void**)&hB, g_hB);
    cudaGetSymbolAddress((void**)&P, g_P);
    cudaGetSymbolAddress((void**)&agg, g_agg);

    proj_kernel<<<592, 256>>>(x, proj_w, proj_b, hA);

    for (int l = 0; l < 3; l++) {
        const float* hin = (l == 1) ? hB : hA;          // l0:A, l1:B, l2:A
        float* hout = (l == 0) ? hB : ((l == 1) ? hA : out);
        const float* w2 = u2w + (size_t)l * 80 * 64;     // rows 0..63 = W2h, 64..79 = W2e
        pk_kernel<<<592, 256>>>(hin, w2, u2b + l * 64, P, agg);
        edge_kernel<<<1184, 256>>>(eidx, eidx + NE, eattr, w2 + 64 * 64, P, agg);
        upd_kernel<<<592, 256>>>(hin, agg, u1w + (size_t)l * 128 * 64, u1b + l * 64, hout);
    }
}

// round 14
// speedup vs baseline: 1.1146x; 1.0161x over previous
#include <cuda_runtime.h>
#include <cuda_fp16.h>
#include <mma.h>

using namespace nvcuda;

#define NN 100000
#define NE 1600000
#define IND 75
#define H 64
#define HB 16

// Scratch (allocation-free rule: __device__ globals)
__device__ __align__(256) float  g_hA[NN * H];
__device__ __align__(256) float  g_hB[NN * H];
__device__ __align__(256) __half g_P[NN * H];
__device__ __align__(256) float  g_agg[NN * H];
__device__ __align__(256) __half g_eat16[(size_t)NE * HB];

// ---- f32x2 packed helpers -------------------------------------------------
typedef unsigned long long u64t;
__device__ __forceinline__ u64t pk2(float lo, float hi) {
    u64t r; asm("mov.b64 %0, {%1, %2};" : "=l"(r) : "f"(lo), "f"(hi)); return r;
}
__device__ __forceinline__ void upk2(u64t v, float& lo, float& hi) {
    asm("mov.b64 {%0, %1}, %2;" : "=f"(lo), "=f"(hi) : "l"(v));
}
__device__ __forceinline__ u64t fma2(u64t a, u64t b, u64t c) {
    u64t d; asm("fma.rn.f32x2 %0, %1, %2, %3;" : "=l"(d) : "l"(a), "l"(b), "l"(c)); return d;
}

// ---------------------------------------------------------------------------
// cvt: eattr fp32 -> fp16, once per launch (identical rounding to old per-layer)
// ---------------------------------------------------------------------------
__global__ __launch_bounds__(256) void cvt_kernel(const float* __restrict__ e,
                                                  __half* __restrict__ o) {
    const size_t i = ((size_t)blockIdx.x * 256 + threadIdx.x) * 8;
    if (i >= (size_t)NE * HB) return;
    const float4 v0 = *(const float4*)(e + i);
    const float4 v1 = *(const float4*)(e + i + 4);
    __half2 h0 = __floats2half2_rn(v0.x, v0.y), h1 = __floats2half2_rn(v0.z, v0.w);
    __half2 h2 = __floats2half2_rn(v1.x, v1.y), h3 = __floats2half2_rn(v1.z, v1.w);
    uint4 p;
    p.x = *(unsigned*)&h0; p.y = *(unsigned*)&h1;
    p.z = *(unsigned*)&h2; p.w = *(unsigned*)&h3;
    *(uint4*)(o + i) = p;
}

// ---------------------------------------------------------------------------
// proj v2: out = x @ W(75x64) + b.  64-node tile, warp = 8 nodes,
// lane = 2 nodes x 8 cols, f32x2 inner. Linear smem (75-stride is
// conflict-free mod 32 across the 8 node addresses).
// ---------------------------------------------------------------------------
__global__ __launch_bounds__(256) void proj_kernel(const float* __restrict__ x,
                                                   const float* __restrict__ w,
                                                   const float* __restrict__ b,
                                                   float* __restrict__ out) {
    __shared__ float sW[IND * H];   // 19.2 KB linear
    __shared__ float sA[64 * IND];  // 19.2 KB linear
    for (int i = threadIdx.x; i < IND * H / 4; i += 256)
        *(float4*)&sW[i * 4] = *(const float4*)&w[i * 4];

    const int lane = threadIdx.x & 31, wid = threadIdx.x >> 5;
    const int nl = lane & 3, cg = lane >> 2;
    const int ln0 = (wid << 3) + (nl << 1), ln1 = ln0 + 1;
    const float4 bb0 = *(const float4*)&b[cg * 8];
    const float4 bb1 = *(const float4*)&b[cg * 8 + 4];
    const int ntiles = (NN + 63) / 64;

    for (int tile = blockIdx.x; tile < ntiles; tile += gridDim.x) {
        const int nbase = tile * 64;
        const int valid = (nbase + 64 <= NN) ? 64 : (NN - nbase);  // 64 or 32
        const int cnt4 = valid * IND / 4;   // divisible (valid % 4 == 0)
        __syncthreads();
        for (int i = threadIdx.x; i < cnt4; i += 256)
            *(float4*)&sA[i * 4] = *(const float4*)(x + (size_t)nbase * IND + i * 4);
        __syncthreads();

        u64t a0c[4] = {pk2(bb0.x, bb0.y), pk2(bb0.z, bb0.w),
                       pk2(bb1.x, bb1.y), pk2(bb1.z, bb1.w)};
        u64t a1c[4] = {a0c[0], a0c[1], a0c[2], a0c[3]};
#pragma unroll 5
        for (int k = 0; k < IND; k++) {
            const ulonglong2 w0 = *(const ulonglong2*)&sW[k * H + cg * 8];
            const ulonglong2 w1 = *(const ulonglong2*)&sW[k * H + cg * 8 + 4];
            const float a0 = sA[ln0 * IND + k];
            const float a1 = sA[ln1 * IND + k];
            const u64t aa0 = pk2(a0, a0), aa1 = pk2(a1, a1);
            a0c[0] = fma2(aa0, w0.x, a0c[0]); a0c[1] = fma2(aa0, w0.y, a0c[1]);
            a0c[2] = fma2(aa0, w1.x, a0c[2]); a0c[3] = fma2(aa0, w1.y, a0c[3]);
            a1c[0] = fma2(aa1, w0.x, a1c[0]); a1c[1] = fma2(aa1, w0.y, a1c[1]);
            a1c[2] = fma2(aa1, w1.x, a1c[2]); a1c[3] = fma2(aa1, w1.y, a1c[3]);
        }
#pragma unroll
        for (int n = 0; n < 2; n++) {
            const int gn = nbase + ((n == 0) ? ln0 : ln1);
            if (gn >= NN) continue;
            const u64t* ac = (n == 0) ? a0c : a1c;
            float f0, f1, f2, f3, f4, f5, f6, f7;
            upk2(ac[0], f0, f1); upk2(ac[1], f2, f3);
            upk2(ac[2], f4, f5); upk2(ac[3], f6, f7);
            float* op = out + (size_t)gn * H + cg * 8;
            *(float4*)op       = make_float4(f0, f1, f2, f3);
            *(float4*)(op + 4) = make_float4(f4, f5, f6, f7);
        }
    }
}

// ---------------------------------------------------------------------------
// pk v3 (R13): P(fp16) = h @ W2h(64x64) + b2, zero agg. 64-node tile.
// ---------------------------------------------------------------------------
__global__ __launch_bounds__(256) void pk_kernel(const float* __restrict__ h,
                                                 const float* __restrict__ w,
                                                 const float* __restrict__ b,
                                                 __half* __restrict__ P,
                                                 float* __restrict__ agg) {
    __shared__ float sW[H][H];       // 16 KB
    __shared__ float sA[64 * 64];    // 16 KB, swizzled
    for (int i = threadIdx.x; i < H * H; i += 256) sW[i >> 6][i & 63] = w[i];

    const int lane = threadIdx.x & 31, wid = threadIdx.x >> 5;
    const int nl = lane & 3, cg = lane >> 2;
    const int ln0 = (wid << 3) + (nl << 1), ln1 = ln0 + 1;
    const int sw0 = (ln0 & 7) * 4, sw1 = (ln1 & 7) * 4;
    const float4 bb0 = *(const float4*)&b[cg * 8];
    const float4 bb1 = *(const float4*)&b[cg * 8 + 4];

    const int snd = threadIdx.x >> 2, sq = threadIdx.x & 3;
    const int ntiles = (NN + 63) / 64;
    const float4 z4 = make_float4(0.f, 0.f, 0.f, 0.f);

    for (int tile = blockIdx.x; tile < ntiles; tile += gridDim.x) {
        const int nbase = tile * 64;
        __syncthreads();
        {
            const int gn = nbase + snd;
            const int ssw = (snd & 7) * 4;
            if (gn < NN) {
#pragma unroll
                for (int j = 0; j < 4; j++) {
                    const int kk = sq * 16 + j * 4;
                    float4 v = *(const float4*)(h + (size_t)gn * H + kk);
                    *(float4*)&sA[snd * 64 + (kk ^ ssw)] = v;
                }
            } else {
#pragma unroll
                for (int j = 0; j < 4; j++)
                    *(float4*)&sA[snd * 64 + ((sq * 16 + j * 4) ^ ssw)] = z4;
            }
        }
        __syncthreads();

        u64t a0c[4] = {pk2(bb0.x, bb0.y), pk2(bb0.z, bb0.w),
                       pk2(bb1.x, bb1.y), pk2(bb1.z, bb1.w)};
        u64t a1c[4] = {a0c[0], a0c[1], a0c[2], a0c[3]};
#pragma unroll 8
        for (int k = 0; k < H; k++) {
            const ulonglong2 w0 = *(const ulonglong2*)&sW[k][cg * 8];
            const ulonglong2 w1 = *(const ulonglong2*)&sW[k][cg * 8 + 4];
            const float a0 = sA[ln0 * 64 + (k ^ sw0)];
            const float a1 = sA[ln1 * 64 + (k ^ sw1)];
            const u64t aa0 = pk2(a0, a0), aa1 = pk2(a1, a1);
            a0c[0] = fma2(aa0, w0.x, a0c[0]); a0c[1] = fma2(aa0, w0.y, a0c[1]);
            a0c[2] = fma2(aa0, w1.x, a0c[2]); a0c[3] = fma2(aa0, w1.y, a0c[3]);
            a1c[0] = fma2(aa1, w0.x, a1c[0]); a1c[1] = fma2(aa1, w0.y, a1c[1]);
            a1c[2] = fma2(aa1, w1.x, a1c[2]); a1c[3] = fma2(aa1, w1.y, a1c[3]);
        }
#pragma unroll
        for (int n = 0; n < 2; n++) {
            const int gn = nbase + ((n == 0) ? ln0 : ln1);
            if (gn >= NN) continue;
            const u64t* ac = (n == 0) ? a0c : a1c;
            float f0, f1, f2, f3, f4, f5, f6, f7;
            upk2(ac[0], f0, f1); upk2(ac[1], f2, f3);
            upk2(ac[2], f4, f5); upk2(ac[3], f6, f7);
            __half2 p0 = __floats2half2_rn(f0, f1);
            __half2 p1 = __floats2half2_rn(f2, f3);
            __half2 p2 = __floats2half2_rn(f4, f5);
            __half2 p3 = __floats2half2_rn(f6, f7);
            uint4 pr;
            pr.x = *(unsigned*)&p0; pr.y = *(unsigned*)&p1;
            pr.z = *(unsigned*)&p2; pr.w = *(unsigned*)&p3;
            *(uint4*)(P + (size_t)gn * H + cg * 8) = pr;
        }
#pragma unroll
        for (int j = 0; j < 4; j++) {
            const int f = threadIdx.x * 4 + j;
            const int node = nbase + (f >> 4);
            if (node < NN)
                *((float4*)(agg + (size_t)nbase * H) + f) = z4;
        }
    }
}

// ---------------------------------------------------------------------------
// edge (HMMA): warp handles 16 edges; pre-converted fp16 eats staged with a
// single coalesced 512B span; wmma vs reg-resident W2e; v4 atomic scatter.
// ---------------------------------------------------------------------------
__global__ __launch_bounds__(256) void edge_kernel(const int* __restrict__ esrc,
                                                   const int* __restrict__ edst,
                                                   const __half* __restrict__ eat16,
                                                   const float* __restrict__ w2e,
                                                   const __half* __restrict__ P,
                                                   float* __restrict__ agg) {
    __shared__ __half sW[HB * H];              // 2048 B
    __shared__ __half sA[8][HB * HB];          // 8 x 512 B
    __shared__ float  sB[8][HB * H];           // 8 x 4096 B

    for (int i = threadIdx.x; i < HB * H; i += 256) sW[i] = __float2half(w2e[i]);
    __syncthreads();

    const int lane = threadIdx.x & 31, wid = threadIdx.x >> 5;
    const int half = lane >> 4, hl = lane & 15;
    const int cbase = hl * 4;

    wmma::fragment<wmma::matrix_b, 16, 16, 16, __half, wmma::row_major> fw[4];
#pragma unroll
    for (int nt = 0; nt < 4; nt++)
        wmma::load_matrix_sync(fw[nt], &sW[nt * 16], H);

    __half* const myA = sA[wid];
    float*  const myB = sB[wid];

    const int gw = blockIdx.x * 8 + wid;
    const int nw = gridDim.x * 8;

    for (int t = gw; t < NE / 16; t += nw) {
        const int ebase = t * 16;
        // stage 16x16 fp16 tile: one coalesced 512B span per warp
        *(uint4*)(myA + lane * 8) =
            *(const uint4*)(eat16 + (size_t)ebase * HB + lane * 8);
        __syncwarp();

        wmma::fragment<wmma::matrix_a, 16, 16, 16, __half, wmma::row_major> fa;
        wmma::load_matrix_sync(fa, myA, HB);
#pragma unroll
        for (int nt = 0; nt < 4; nt++) {
            wmma::fragment<wmma::accumulator, 16, 16, 16, float> fc;
            wmma::fill_fragment(fc, 0.f);
            wmma::mma_sync(fc, fa, fw[nt], fc);
            wmma::store_matrix_sync(&myB[nt * 16], fc, H, wmma::mem_row_major);
        }
        __syncwarp();

#pragma unroll
        for (int r = 0; r < 8; r++) {
            const int el = 2 * r + half;
            const int e = ebase + el;
            const int src = esrc[e];
            const int dst = edst[e];
            if ((unsigned)src >= NN || (unsigned)dst >= NN) continue;

            const float4 bv = *(const float4*)(myB + el * H + cbase);
            const uint2 praw = *(const uint2*)(P + (size_t)src * H + cbase);
            const float2 pa = __half22float2(*(const __half2*)&praw.x);
            const float2 pb = __half22float2(*(const __half2*)&praw.y);

            float m0 = pa.x + bv.x, m1 = pa.y + bv.y;
            float m2 = pb.x + bv.z, m3 = pb.y + bv.w;
            m0 = fmaxf(m0, 0.1f * m0);
            m1 = fmaxf(m1, 0.1f * m1);
            m2 = fmaxf(m2, 0.1f * m2);
            m3 = fmaxf(m3, 0.1f * m3);

            float* dp = agg + (size_t)dst * H + cbase;
            asm volatile("red.global.add.v4.f32 [%0], {%1, %2, %3, %4};"
                         :: "l"(dp), "f"(m0), "f"(m1), "f"(m2), "f"(m3)
                         : "memory");
        }
        __syncwarp();
    }
}

// ---------------------------------------------------------------------------
// upd v3 (R13): out = concat(h, agg) @ W1(128x64) + b1. 64-node tile.
// ---------------------------------------------------------------------------
__global__ __launch_bounds__(256) void upd_kernel(const float* __restrict__ h,
                                                  const float* __restrict__ agg,
                                                  const float* __restrict__ w,
                                                  const float* __restrict__ b,
                                                  float* __restrict__ out) {
    __shared__ float sW[2 * H][H];   // 32 KB
    __shared__ float sA[64 * 64];    // 16 KB, swizzled
    for (int i = threadIdx.x; i < 2 * H * H; i += 256) sW[i >> 6][i & 63] = w[i];

    const int lane = threadIdx.x & 31, wid = threadIdx.x >> 5;
    const int nl = lane & 3, cg = lane >> 2;
    const int ln0 = (wid << 3) + (nl << 1), ln1 = ln0 + 1;
    const int sw0 = (ln0 & 7) * 4, sw1 = (ln1 & 7) * 4;
    const float4 bb0 = *(const float4*)&b[cg * 8];
    const float4 bb1 = *(const float4*)&b[cg * 8 + 4];

    const int snd = threadIdx.x >> 2, sq = threadIdx.x & 3;
    const int ntiles = (NN + 63) / 64;
    const float4 z4 = make_float4(0.f, 0.f, 0.f, 0.f);

    for (int tile = blockIdx.x; tile < ntiles; tile += gridDim.x) {
        const int nbase = tile * 64;
        u64t a0c[4] = {pk2(bb0.x, bb0.y), pk2(bb0.z, bb0.w),
                       pk2(bb1.x, bb1.y), pk2(bb1.z, bb1.w)};
        u64t a1c[4] = {a0c[0], a0c[1], a0c[2], a0c[3]};

#pragma unroll
        for (int ch = 0; ch < 2; ch++) {
            const float* srcm = (ch == 0) ? h : agg;
            __syncthreads();
            {
                const int gn = nbase + snd;
                const int ssw = (snd & 7) * 4;
                if (gn < NN) {
#pragma unroll
                    for (int j = 0; j < 4; j++) {
                        const int kk = sq * 16 + j * 4;
                        float4 v = *(const float4*)(srcm + (size_t)gn * H + kk);
                        *(float4*)&sA[snd * 64 + (kk ^ ssw)] = v;
                    }
                } else {
#pragma unroll
                    for (int j = 0; j < 4; j++)
                        *(float4*)&sA[snd * 64 + ((sq * 16 + j * 4) ^ ssw)] = z4;
                }
            }
            __syncthreads();

#pragma unroll 8
            for (int k = 0; k < H; k++) {
                const int wrow = ch * H + k;
                const ulonglong2 w0 = *(const ulonglong2*)&sW[wrow][cg * 8];
                const ulonglong2 w1 = *(const ulonglong2*)&sW[wrow][cg * 8 + 4];
                const float a0 = sA[ln0 * 64 + (k ^ sw0)];
                const float a1 = sA[ln1 * 64 + (k ^ sw1)];
                const u64t aa0 = pk2(a0, a0), aa1 = pk2(a1, a1);
                a0c[0] = fma2(aa0, w0.x, a0c[0]); a0c[1] = fma2(aa0, w0.y, a0c[1]);
                a0c[2] = fma2(aa0, w1.x, a0c[2]); a0c[3] = fma2(aa0, w1.y, a0c[3]);
                a1c[0] = fma2(aa1, w0.x, a1c[0]); a1c[1] = fma2(aa1, w0.y, a1c[1]);
                a1c[2] = fma2(aa1, w1.x, a1c[2]); a1c[3] = fma2(aa1, w1.y, a1c[3]);
            }
        }

#pragma unroll
        for (int n = 0; n < 2; n++) {
            const int gn = nbase + ((n == 0) ? ln0 : ln1);
            if (gn >= NN) continue;
            const u64t* ac = (n == 0) ? a0c : a1c;
            float f0, f1, f2, f3, f4, f5, f6, f7;
            upk2(ac[0], f0, f1); upk2(ac[1], f2, f3);
            upk2(ac[2], f4, f5); upk2(ac[3], f6, f7);
            float* op = out + (size_t)gn * H + cg * 8;
            *(float4*)op       = make_float4(f0, f1, f2, f3);
            *(float4*)(op + 4) = make_float4(f4, f5, f6, f7);
        }
    }
}

// ---------------------------------------------------------------------------
extern "C" void kernel_launch(void* const* d_in, const int* in_sizes, int n_in,
                              void* d_out, int out_size) {
    const float* x      = (const float*)d_in[0];   // [100000, 75]
    const int*   eidx   = (const int*)d_in[1];     // [2, 1600000] (int64 -> int32)
    const float* eattr  = (const float*)d_in[2];   // [1600000, 16]
    const float* proj_w = (const float*)d_in[3];
    const float* proj_b = (const float*)d_in[4];
    const float* u2w    = (const float*)d_in[5];   // [3, 80, 64]
    const float* u2b    = (const float*)d_in[6];
    const float* u1w    = (const float*)d_in[7];   // [3, 128, 64]
    const float* u1b    = (const float*)d_in[8];
    float*       out    = (float*)d_out;           // [100000, 64]

    float *hA, *hB, *agg;
    __half *P, *eat16;
    cudaGetSymbolAddress((void**)&hA, g_hA);
    cudaGetSymbolAddress((void**)&hB, g_hB);
    cudaGetSymbolAddress((void**)&P, g_P);
    cudaGetSymbolAddress((void**)&agg, g_agg);
    cudaGetSymbolAddress((void**)&eat16, g_eat16);

    cvt_kernel<<<(NE * HB / 8 + 255) / 256, 256>>>(eattr, eat16);
    proj_kernel<<<592, 256>>>(x, proj_w, proj_b, hA);

    for (int l = 0; l < 3; l++) {
        const float* hin = (l == 1) ? hB : hA;          // l0:A, l1:B, l2:A
        float* hout = (l == 0) ? hB : ((l == 1) ? hA : out);
        const float* w2 = u2w + (size_t)l * 80 * 64;     // rows 0..63 = W2h, 64..79 = W2e
        pk_kernel<<<592, 256>>>(hin, w2, u2b + l * 64, P, agg);
        edge_kernel<<<1184, 256>>>(eidx, eidx + NE, eat16, w2 + 64 * 64, P, agg);
        upd_kernel<<<592, 256>>>(hin, agg, u1w + (size_t)l * 128 * 64, u1b + l * 64, hout);
    }
}